// round 10
// baseline (speedup 1.0000x reference)
#include <cuda_runtime.h>
#include <cuda_bf16.h>
#include <cstdint>

// ---------------------------------------------------------------------------
// CorrelationModule on sm_100 (base target -- NO tcgen05, NO f32x2):
//   BN+ReLU -> conv3x3 as mma.sync bf16 split-precision implicit GEMM
//   (CTA = 64w x 128cout, 256 thr, 2 CTAs/SM) -> fused channel L2 norm
//   (bf16 hi/lo) -> 9x9 dilated correlation on mma.sync (parity Toeplitz).
// ---------------------------------------------------------------------------

#define BB    4
#define GG    4
#define CI    128
#define CO    128
#define HH    64
#define WW    128
#define NIMG  16
#define PATCH 9
#define PADC  8

typedef unsigned int u32;

// ------------------------------ device scratch -----------------------------
__device__ __align__(128) __nv_bfloat16  g_nfh[NIMG * HH * WW * CO];     // 32 MB
__device__ __align__(128) __nv_bfloat16  g_nfl[NIMG * HH * WW * CO];     // 32 MB
__device__ __align__(128) __nv_bfloat16  g_act_hi[NIMG * HH * WW * CI];  // 32 MB
__device__ __align__(128) __nv_bfloat16  g_act_lo[NIMG * HH * WW * CI];  // 32 MB
__device__ __align__(128) __nv_bfloat16  g_wb[36 * 128 * 64];
__device__ float g_bn_a[CI];
__device__ float g_bn_b[CI];

// ------------------------------ helpers ------------------------------------
__device__ __forceinline__ u32 smem_u32(const void* p) {
    u32 a;
    asm("{ .reg .u64 t; cvta.to.shared.u64 t, %1; cvt.u32.u64 %0, t; }"
        : "=r"(a) : "l"(p));
    return a;
}

#define LDM4(r, addr) \
    asm volatile("ldmatrix.sync.aligned.m8n8.x4.shared.b16 {%0,%1,%2,%3}, [%4];" \
        : "=r"((r)[0]), "=r"((r)[1]), "=r"((r)[2]), "=r"((r)[3]) : "r"(addr))
#define LDM2(r, addr) \
    asm volatile("ldmatrix.sync.aligned.m8n8.x2.shared.b16 {%0,%1}, [%2];" \
        : "=r"((r)[0]), "=r"((r)[1]) : "r"(addr))

#define MMA16816(d, a, b0_, b1_) \
    asm volatile("mma.sync.aligned.m16n8k16.row.col.f32.bf16.bf16.f32 " \
        "{%0,%1,%2,%3}, {%4,%5,%6,%7}, {%8,%9}, {%0,%1,%2,%3};" \
        : "+f"((d)[0]), "+f"((d)[1]), "+f"((d)[2]), "+f"((d)[3]) \
        : "r"((a)[0]), "r"((a)[1]), "r"((a)[2]), "r"((a)[3]), "r"(b0_), "r"(b1_))

#define CP_ASYNC16(dst, src, sz) \
    asm volatile("cp.async.cg.shared.global [%0], [%1], 16, %2;" \
                 :: "r"(dst), "l"(src), "r"(sz) : "memory")
#define CP_COMMIT() asm volatile("cp.async.commit_group;" ::: "memory")
#define CP_WAIT1()  asm volatile("cp.async.wait_group 1;" ::: "memory")
#define CP_WAIT0()  asm volatile("cp.async.wait_group 0;" ::: "memory")

__device__ __forceinline__ u32 pack_bf2(float a, float b) {
    __nv_bfloat16 x = __float2bfloat16(a), y = __float2bfloat16(b);
    return (u32)__bfloat16_as_ushort(x) | ((u32)__bfloat16_as_ushort(y) << 16);
}

// ---------------------------------------------------------------------------
__global__ void prep_bn_kernel(const float* __restrict__ gamma,
                               const float* __restrict__ beta,
                               const float* __restrict__ mean,
                               const float* __restrict__ var) {
    int c = threadIdx.x;
    if (c < CI) {
        float a = gamma[c] * rsqrtf(var[c] + 1e-5f);
        g_bn_a[c] = a;
        g_bn_b[c] = beta[c] - mean[c] * a;
    }
}

// ---------------------------------------------------------------------------
__global__ void prep_w_kernel(const float* __restrict__ convw) {
    int im   = blockIdx.x;              // 0..35
    int sp   = im & 1;
    int half = (im >> 1) & 1;
    int tap  = im >> 2;
    int dy = tap / 3, dx = tap % 3;
    __nv_bfloat16* base = g_wb + (size_t)im * 8192;
    for (int t = threadIdx.x; t < 128 * 64; t += 256) {
        int cout = t >> 6;
        int cl   = t & 63;
        int cin  = half * 64 + cl;
        float wv = convw[(cout * CI + cin) * 9 + dy * 3 + dx];
        __nv_bfloat16 hi = __float2bfloat16(wv);
        base[t] = (sp == 0) ? hi : __float2bfloat16(wv - __bfloat162float(hi));
    }
}

// ---------------------------------------------------------------------------
__global__ __launch_bounds__(256)
void act_split_kernel(const float* __restrict__ x) {
    const int img = blockIdx.x, h = blockIdx.y;
    const int g = img >> 2, b = img & 3;
    __shared__ float s[64 * 133];
    const int tid = threadIdx.x;
    const int c2 = tid >> 7;
    const int wl = tid & 127;

    for (int pass = 0; pass < 2; pass++) {
        __syncthreads();
        for (int co = 0; co < 64; co += 2) {
            int cl  = co + c2;
            int cin = pass * 64 + cl;
            float xv = x[(((size_t)b * 512 + g * 128 + cin) * HH + h) * WW + wl];
            s[cl * 133 + wl] = fmaxf(fmaf(xv, g_bn_a[cin], g_bn_b[cin]), 0.f);
        }
        __syncthreads();
        for (int t = tid; t < 2048; t += 256) {
            int w  = t >> 4;
            int cc = t & 15;
            float v0 = s[(cc * 4 + 0) * 133 + w];
            float v1 = s[(cc * 4 + 1) * 133 + w];
            float v2 = s[(cc * 4 + 2) * 133 + w];
            float v3 = s[(cc * 4 + 3) * 133 + w];
            __nv_bfloat16 h0 = __float2bfloat16(v0), h1 = __float2bfloat16(v1);
            __nv_bfloat16 h2 = __float2bfloat16(v2), h3 = __float2bfloat16(v3);
            uint2 hv, lv;
            hv.x = (u32)__bfloat16_as_ushort(h0) | ((u32)__bfloat16_as_ushort(h1) << 16);
            hv.y = (u32)__bfloat16_as_ushort(h2) | ((u32)__bfloat16_as_ushort(h3) << 16);
            lv.x = pack_bf2(v0 - __bfloat162float(h0), v1 - __bfloat162float(h1));
            lv.y = pack_bf2(v2 - __bfloat162float(h2), v3 - __bfloat162float(h3));
            size_t e = (((size_t)img * HH + h) * WW + w) * CI + pass * 64 + cc * 4;
            *(uint2*)(g_act_hi + e) = hv;
            *(uint2*)(g_act_lo + e) = lv;
        }
    }
}

// ---------------------------------------------------------------------------
// conv_kernel: CTA = (img, h, whalf): M=64 w x N=128 cout, 256 thr, 8 warps
// (2M x 4N), warp tile 32x32. 18 x K=64 stages; stage = Ahi/Alo [64][128B]
// + Bhi/Blo [128][128B] = 48KB, double buffered (96KB) -> 2 CTAs/SM.
// ---------------------------------------------------------------------------
#define CONV_STAGE 49152
#define CONV_SMEM  (2 * CONV_STAGE)

__global__ __launch_bounds__(256, 2)
void conv_kernel() {
    extern __shared__ char smem[];
    const u32 sb = smem_u32(smem);
    const int tid  = threadIdx.x;
    const int wid  = tid >> 5;
    const int lane = tid & 31;
    const int img   = blockIdx.x;
    const int h     = blockIdx.y;
    const int wbase = blockIdx.z * 64;   // w half
    const int wm = wid & 1;              // M warp 0..1 (32 rows each)
    const int wn = wid >> 1;             // N warp 0..3 (32 couts each)
    const int qg = lane >> 2;
    const int qt = lane & 3;

    const int a_r0 = (lane & 7) + ((lane >> 3) & 1) * 8;
    const int a_cs = (lane >> 4) & 1;
    const int b_r0 = (lane & 7) + ((lane >> 4) & 1) * 8;
    const int b_cs = (lane >> 3) & 1;

    float acc[2][4][4];
#pragma unroll
    for (int i = 0; i < 2; i++)
#pragma unroll
        for (int j = 0; j < 4; j++)
#pragma unroll
            for (int c = 0; c < 4; c++) acc[i][j][c] = 0.f;

    auto issue_stage = [&](int s) {
        const int tap = s >> 1, half = s & 1;
        const int dy = tap / 3, dx = tap % 3;
        const int hsrc = h + dy - 1;
        const bool hok = (unsigned)hsrc < (unsigned)HH;
        const u32 buf = sb + (u32)(s & 1) * CONV_STAGE;
        for (int c = tid; c < 3072; c += 256) {
            if (c < 1024) {                      // A: sp, row(64), ch
                const int sp  = c >> 9;
                const int q   = c & 511;
                const int row = q >> 3;
                const int ch  = q & 7;
                const int wsrc = wbase + row + dx - 1;
                const bool ok = hok && (unsigned)wsrc < (unsigned)WW;
                const __nv_bfloat16* base = sp ? g_act_lo : g_act_hi;
                const __nv_bfloat16* src = base +
                    ((((size_t)img * HH + (ok ? hsrc : 0)) * WW
                      + (ok ? wsrc : 0)) * CI + half * 64 + ch * 8);
                const u32 dst = buf + (u32)sp * 8192u + (u32)row * 128u
                              + (u32)((ch ^ (row & 7)) << 4);
                CP_ASYNC16(dst, src, ok ? 16u : 0u);
            } else {                             // B: sp, row(128), ch
                const int c2  = c - 1024;
                const int sp  = c2 >> 10;
                const int q   = c2 & 1023;
                const int row = q >> 3;
                const int ch  = q & 7;
                const int tile = (tap * 2 + half) * 2 + sp;
                const __nv_bfloat16* src = g_wb + (size_t)tile * 8192 + q * 8;
                const u32 dst = buf + 16384u + (u32)sp * 16384u + (u32)row * 128u
                              + (u32)((ch ^ (row & 7)) << 4);
                CP_ASYNC16(dst, src, 16u);
            }
        }
        CP_COMMIT();
    };

    issue_stage(0);
    for (int s = 0; s < 18; s++) {
        if (s + 1 < 18) { issue_stage(s + 1); CP_WAIT1(); }
        else            { CP_WAIT0(); }
        __syncthreads();
        const u32 buf = sb + (u32)(s & 1) * CONV_STAGE;
        const u32 ah_b = buf, al_b = buf + 8192u;
        const u32 bh_b = buf + 16384u, bl_b = buf + 32768u;
#pragma unroll
        for (int kk = 0; kk < 4; kk++) {
            u32 Ah[2][4], Al[2][4], Bh[2][4], Bl[2][4];
#pragma unroll
            for (int i = 0; i < 2; i++) {
                const int row = wm * 32 + i * 16 + a_r0;   // < 64
                const int ch  = kk * 2 + a_cs;
                const u32 off = (u32)row * 128u + (u32)((ch ^ (row & 7)) << 4);
                LDM4(Ah[i], ah_b + off);
                LDM4(Al[i], al_b + off);
            }
#pragma unroll
            for (int jj = 0; jj < 2; jj++) {
                const int row = wn * 32 + jj * 16 + b_r0;  // < 128
                const int ch  = kk * 2 + b_cs;
                const u32 off = (u32)row * 128u + (u32)((ch ^ (row & 7)) << 4);
                LDM4(Bh[jj], bh_b + off);
                LDM4(Bl[jj], bl_b + off);
            }
#pragma unroll
            for (int i = 0; i < 2; i++)
#pragma unroll
                for (int j = 0; j < 4; j++) {
                    const u32 bh0 = Bh[j >> 1][(j & 1) * 2];
                    const u32 bh1 = Bh[j >> 1][(j & 1) * 2 + 1];
                    const u32 bl0 = Bl[j >> 1][(j & 1) * 2];
                    const u32 bl1 = Bl[j >> 1][(j & 1) * 2 + 1];
                    MMA16816(acc[i][j], Ah[i], bh0, bh1);
                    MMA16816(acc[i][j], Al[i], bh0, bh1);
                    MMA16816(acc[i][j], Ah[i], bl0, bl1);
                }
        }
        __syncthreads();
    }

    // ---- fused channel L2 norm epilogue (bf16 hi/lo output) ----
    float* part = (float*)smem;   // [4 wn][64 w]
#pragma unroll
    for (int i = 0; i < 2; i++)
#pragma unroll
        for (int rh = 0; rh < 2; rh++) {
            float ssum = 0.f;
#pragma unroll
            for (int j = 0; j < 4; j++) {
                float c0 = acc[i][j][rh * 2], c1 = acc[i][j][rh * 2 + 1];
                ssum = fmaf(c0, c0, fmaf(c1, c1, ssum));
            }
            ssum += __shfl_xor_sync(0xFFFFFFFFu, ssum, 1);
            ssum += __shfl_xor_sync(0xFFFFFFFFu, ssum, 2);
            if (qt == 0)
                part[wn * 64 + wm * 32 + i * 16 + rh * 8 + qg] = ssum;
        }
    __syncthreads();
#pragma unroll
    for (int i = 0; i < 2; i++)
#pragma unroll
        for (int rh = 0; rh < 2; rh++) {
            const int r = wm * 32 + i * 16 + rh * 8 + qg;  // 0..63
            const float inv = rsqrtf(part[r] + part[64 + r]
                                     + part[128 + r] + part[192 + r]);
            const size_t base = (((size_t)img * HH + h) * WW + wbase + r) * CO
                              + wn * 32;
#pragma unroll
            for (int j = 0; j < 4; j++) {
                float v0 = acc[i][j][rh * 2] * inv;
                float v1 = acc[i][j][rh * 2 + 1] * inv;
                __nv_bfloat16 h0 = __float2bfloat16(v0);
                __nv_bfloat16 h1 = __float2bfloat16(v1);
                u32 hv = (u32)__bfloat16_as_ushort(h0)
                       | ((u32)__bfloat16_as_ushort(h1) << 16);
                u32 lv = pack_bf2(v0 - __bfloat162float(h0),
                                  v1 - __bfloat162float(h1));
                *(u32*)(g_nfh + base + j * 8 + qt * 2) = hv;
                *(u32*)(g_nfl + base + j * 8 + qt * 2) = lv;
            }
        }
}

// ---------------------------------------------------------------------------
// corr_kernel (proven R7 tensor version, unchanged)
// ---------------------------------------------------------------------------
#define CORR_F2OFF  65536
#define CORR_F2BUF  36864
#define CORR_OUTOFF (65536 + 2 * 36864)
#define CORR_SMEM   (65536 + 2 * 36864 + 4800)

__global__ __launch_bounds__(256, 1)
void corr_kernel(float* __restrict__ out) {
    extern __shared__ char smem[];
    const u32 sb = smem_u32(smem);
    const int tid  = threadIdx.x;
    const int wid  = tid >> 5;
    const int lane = tid & 31;
    const int h    = blockIdx.x;
    const int pb   = blockIdx.y;
    const int pair = pb >> 2, b = pb & 3;
    const int img1 = pair * 4 + b;
    const int img2 = img1 + 4;
    const int pp   = wid & 1;
    const int idx  = wid >> 1;
    const int qg = lane >> 2, qt = lane & 3;
    const int a_r0 = (lane & 7) + ((lane >> 3) & 1) * 8;
    const int a_cs = (lane >> 4) & 1;
    const int b_r0 = (lane & 7) + ((lane >> 4) & 1) * 8;
    const int b_cs = (lane >> 3) & 1;

    for (int t = tid; t < 4096; t += 256) {
        const int ch  = t & 7;
        const int row = (t >> 3) & 63;
        const int par = (t >> 9) & 1;
        const int sp  = (t >> 10) & 1;
        const int chf = (t >> 11) & 1;
        const int w   = par + 2 * row;
        const __nv_bfloat16* src = (sp ? g_nfl : g_nfh) +
            ((((size_t)img1 * HH + h) * WW + w) * CO + chf * 64 + ch * 8);
        const u32 dst = sb + (u32)((((chf * 2 + sp) * 2 + par) * 64 + row) * 128)
                      + (u32)((ch ^ (row & 7)) << 4);
        CP_ASYNC16(dst, src, 16u);
    }

    auto issue_f2 = [&](int it) {
        const int py  = it >> 1;
        const int chf = it & 1;
        const int h2  = h + 2 * py - 8;
        const bool hok = (unsigned)h2 < (unsigned)HH;
        const u32 buf = sb + CORR_F2OFF + (u32)(it & 1) * CORR_F2BUF;
        for (int t = tid; t < 2304; t += 256) {
            const int ch   = t & 7;
            const int rr   = t >> 3;
            const int row  = rr % 72;
            const int rest = rr / 72;
            const int par = rest & 1, sp = rest >> 1;
            const int w2 = par + 2 * (row - 4);
            const bool ok = hok && (unsigned)w2 < (unsigned)WW;
            const __nv_bfloat16* src = (sp ? g_nfl : g_nfh) +
                ((((size_t)img2 * HH + (ok ? h2 : 0)) * WW + (ok ? w2 : 0)) * CO
                 + chf * 64 + ch * 8);
            const u32 dst = buf + (u32)(((sp * 2 + par) * 72 + row) * 128)
                          + (u32)((ch ^ (row & 7)) << 4);
            CP_ASYNC16(dst, src, ok ? 16u : 0u);
        }
        CP_COMMIT();
    };

    issue_f2(0);
    float acc[3][4];
    float* ost = (float*)(smem + CORR_OUTOFF);

    for (int it = 0; it < 18; it++) {
        if (it + 1 < 18) { issue_f2(it + 1); CP_WAIT1(); }
        else             { CP_WAIT0(); }
        __syncthreads();
        const int chf = it & 1;
        if (chf == 0) {
#pragma unroll
            for (int t2 = 0; t2 < 3; t2++)
#pragma unroll
                for (int c = 0; c < 4; c++) acc[t2][c] = 0.f;
        }
        const u32 f2b = sb + CORR_F2OFF + (u32)(it & 1) * CORR_F2BUF;
#pragma unroll
        for (int kk = 0; kk < 4; kk++) {
            u32 Ah[4], Al[4], Bh[6], Bl[6];
            {
                const int row = idx * 16 + a_r0;
                const int ch  = kk * 2 + a_cs;
                const u32 swz = (u32)((ch ^ (row & 7)) << 4);
                const u32 oh = sb + (u32)((((chf * 2 + 0) * 2 + pp) * 64 + row) * 128) + swz;
                const u32 ol = sb + (u32)((((chf * 2 + 1) * 2 + pp) * 64 + row) * 128) + swz;
                LDM4(Ah, oh);
                LDM4(Al, ol);
            }
            {
                const int row = idx * 16 + b_r0;
                const int ch  = kk * 2 + b_cs;
                const u32 swz = (u32)((ch ^ (row & 7)) << 4);
                const u32 oh = f2b + (u32)(((0 * 2 + pp) * 72 + row) * 128) + swz;
                const u32 ol = f2b + (u32)(((1 * 2 + pp) * 72 + row) * 128) + swz;
                LDM4(Bh, oh);
                LDM4(Bl, ol);
            }
            {
                const int row = idx * 16 + 16 + (lane & 7);
                const int ch  = kk * 2 + ((lane >> 3) & 1);
                const u32 swz = (u32)((ch ^ (row & 7)) << 4);
                const u32 oh = f2b + (u32)(((0 * 2 + pp) * 72 + row) * 128) + swz;
                const u32 ol = f2b + (u32)(((1 * 2 + pp) * 72 + row) * 128) + swz;
                LDM2(Bh + 4, oh);
                LDM2(Bl + 4, ol);
            }
#pragma unroll
            for (int t2 = 0; t2 < 3; t2++) {
                const u32 bh0 = Bh[t2 * 2], bh1 = Bh[t2 * 2 + 1];
                const u32 bl0 = Bl[t2 * 2], bl1 = Bl[t2 * 2 + 1];
                MMA16816(acc[t2], Ah, bh0, bh1);
                MMA16816(acc[t2], Al, bh0, bh1);
                MMA16816(acc[t2], Ah, bl0, bl1);
            }
        }
        if (chf == 1) {
            const int py = it >> 1;
#pragma unroll
            for (int t2 = 0; t2 < 3; t2++)
#pragma unroll
                for (int reg = 0; reg < 4; reg++) {
                    const int r  = qg + 8 * (reg >> 1);
                    const int j  = 8 * t2 + 2 * qt + (reg & 1);
                    const int px = j - r;
                    if ((unsigned)px <= 8u) {
                        const int w = pp + 2 * (16 * idx + r);
                        ost[px * 132 + w] = acc[t2][reg];
                    }
                }
            __syncthreads();
            for (int t2 = tid; t2 < 1152; t2 += 256) {
                const int px = t2 >> 7;
                const int w  = t2 & 127;
                out[(((size_t)b * 243 + pair * 81 + py * 9 + px) * HH + h) * WW + w]
                    = ost[px * 132 + w];
            }
        }
        __syncthreads();
    }
}

// ---------------------------------------------------------------------------
extern "C" void kernel_launch(void* const* d_in, const int* in_sizes, int n_in,
                              void* d_out, int out_size) {
    const float* x     = (const float*)d_in[0];
    const float* gamma = (const float*)d_in[1];
    const float* beta  = (const float*)d_in[2];
    const float* mean  = (const float*)d_in[3];
    const float* var   = (const float*)d_in[4];
    const float* convw = (const float*)d_in[5];
    float* out = (float*)d_out;

    cudaFuncSetAttribute(conv_kernel,
                         cudaFuncAttributeMaxDynamicSharedMemorySize, CONV_SMEM);
    cudaFuncSetAttribute(corr_kernel,
                         cudaFuncAttributeMaxDynamicSharedMemorySize, CORR_SMEM);

    prep_bn_kernel<<<1, 128>>>(gamma, beta, mean, var);
    prep_w_kernel<<<36, 256>>>(convw);
    act_split_kernel<<<dim3(NIMG, HH), 256>>>(x);
    conv_kernel<<<dim3(NIMG, HH, 2), 256, CONV_SMEM>>>();
    corr_kernel<<<dim3(HH, 3 * BB), 256, CORR_SMEM>>>(out);
}

// round 11
// speedup vs baseline: 1.0316x; 1.0316x over previous
#include <cuda_runtime.h>
#include <cuda_bf16.h>
#include <cstdint>

// ---------------------------------------------------------------------------
// CorrelationModule on sm_100 (base target -- NO tcgen05, NO f32x2):
//   BN+ReLU -> conv3x3 as mma.sync bf16 split-precision implicit GEMM
//   (R7 geometry, 3-deep cp.async pipeline) -> fused channel L2 norm
//   (bf16 hi/lo) -> 9x9 dilated correlation on mma.sync (parity Toeplitz,
//   3-deep f2 ring).
// ---------------------------------------------------------------------------

#define BB    4
#define GG    4
#define CI    128
#define CO    128
#define HH    64
#define WW    128
#define NIMG  16
#define PATCH 9
#define PADC  8

typedef unsigned int u32;

// ------------------------------ device scratch -----------------------------
__device__ __align__(128) __nv_bfloat16  g_nfh[NIMG * HH * WW * CO];     // 32 MB
__device__ __align__(128) __nv_bfloat16  g_nfl[NIMG * HH * WW * CO];     // 32 MB
__device__ __align__(128) __nv_bfloat16  g_act_hi[NIMG * HH * WW * CI];  // 32 MB
__device__ __align__(128) __nv_bfloat16  g_act_lo[NIMG * HH * WW * CI];  // 32 MB
__device__ __align__(128) __nv_bfloat16  g_wb[36 * 128 * 64];
__device__ float g_bn_a[CI];
__device__ float g_bn_b[CI];

// ------------------------------ helpers ------------------------------------
__device__ __forceinline__ u32 smem_u32(const void* p) {
    u32 a;
    asm("{ .reg .u64 t; cvta.to.shared.u64 t, %1; cvt.u32.u64 %0, t; }"
        : "=r"(a) : "l"(p));
    return a;
}

#define LDM4(r, addr) \
    asm volatile("ldmatrix.sync.aligned.m8n8.x4.shared.b16 {%0,%1,%2,%3}, [%4];" \
        : "=r"((r)[0]), "=r"((r)[1]), "=r"((r)[2]), "=r"((r)[3]) : "r"(addr))
#define LDM2(r, addr) \
    asm volatile("ldmatrix.sync.aligned.m8n8.x2.shared.b16 {%0,%1}, [%2];" \
        : "=r"((r)[0]), "=r"((r)[1]) : "r"(addr))

#define MMA16816(d, a, b0_, b1_) \
    asm volatile("mma.sync.aligned.m16n8k16.row.col.f32.bf16.bf16.f32 " \
        "{%0,%1,%2,%3}, {%4,%5,%6,%7}, {%8,%9}, {%0,%1,%2,%3};" \
        : "+f"((d)[0]), "+f"((d)[1]), "+f"((d)[2]), "+f"((d)[3]) \
        : "r"((a)[0]), "r"((a)[1]), "r"((a)[2]), "r"((a)[3]), "r"(b0_), "r"(b1_))

#define CP_ASYNC16(dst, src, sz) \
    asm volatile("cp.async.cg.shared.global [%0], [%1], 16, %2;" \
                 :: "r"(dst), "l"(src), "r"(sz) : "memory")
#define CP_COMMIT() asm volatile("cp.async.commit_group;" ::: "memory")
#define CP_WAIT2()  asm volatile("cp.async.wait_group 2;" ::: "memory")
#define CP_WAIT1()  asm volatile("cp.async.wait_group 1;" ::: "memory")
#define CP_WAIT0()  asm volatile("cp.async.wait_group 0;" ::: "memory")

__device__ __forceinline__ u32 pack_bf2(float a, float b) {
    __nv_bfloat16 x = __float2bfloat16(a), y = __float2bfloat16(b);
    return (u32)__bfloat16_as_ushort(x) | ((u32)__bfloat16_as_ushort(y) << 16);
}

// ---------------------------------------------------------------------------
__global__ void prep_bn_kernel(const float* __restrict__ gamma,
                               const float* __restrict__ beta,
                               const float* __restrict__ mean,
                               const float* __restrict__ var) {
    int c = threadIdx.x;
    if (c < CI) {
        float a = gamma[c] * rsqrtf(var[c] + 1e-5f);
        g_bn_a[c] = a;
        g_bn_b[c] = beta[c] - mean[c] * a;
    }
}

// ---------------------------------------------------------------------------
__global__ void prep_w_kernel(const float* __restrict__ convw) {
    int im   = blockIdx.x;              // 0..35
    int sp   = im & 1;
    int half = (im >> 1) & 1;
    int tap  = im >> 2;
    int dy = tap / 3, dx = tap % 3;
    __nv_bfloat16* base = g_wb + (size_t)im * 8192;
    for (int t = threadIdx.x; t < 128 * 64; t += 256) {
        int cout = t >> 6;
        int cl   = t & 63;
        int cin  = half * 64 + cl;
        float wv = convw[(cout * CI + cin) * 9 + dy * 3 + dx];
        __nv_bfloat16 hi = __float2bfloat16(wv);
        base[t] = (sp == 0) ? hi : __float2bfloat16(wv - __bfloat162float(hi));
    }
}

// ---------------------------------------------------------------------------
__global__ __launch_bounds__(256)
void act_split_kernel(const float* __restrict__ x) {
    const int img = blockIdx.x, h = blockIdx.y;
    const int g = img >> 2, b = img & 3;
    __shared__ float s[64 * 133];
    const int tid = threadIdx.x;
    const int c2 = tid >> 7;
    const int wl = tid & 127;

    for (int pass = 0; pass < 2; pass++) {
        __syncthreads();
        for (int co = 0; co < 64; co += 2) {
            int cl  = co + c2;
            int cin = pass * 64 + cl;
            float xv = x[(((size_t)b * 512 + g * 128 + cin) * HH + h) * WW + wl];
            s[cl * 133 + wl] = fmaxf(fmaf(xv, g_bn_a[cin], g_bn_b[cin]), 0.f);
        }
        __syncthreads();
        for (int t = tid; t < 2048; t += 256) {
            int w  = t >> 4;
            int cc = t & 15;
            float v0 = s[(cc * 4 + 0) * 133 + w];
            float v1 = s[(cc * 4 + 1) * 133 + w];
            float v2 = s[(cc * 4 + 2) * 133 + w];
            float v3 = s[(cc * 4 + 3) * 133 + w];
            __nv_bfloat16 h0 = __float2bfloat16(v0), h1 = __float2bfloat16(v1);
            __nv_bfloat16 h2 = __float2bfloat16(v2), h3 = __float2bfloat16(v3);
            uint2 hv, lv;
            hv.x = (u32)__bfloat16_as_ushort(h0) | ((u32)__bfloat16_as_ushort(h1) << 16);
            hv.y = (u32)__bfloat16_as_ushort(h2) | ((u32)__bfloat16_as_ushort(h3) << 16);
            lv.x = pack_bf2(v0 - __bfloat162float(h0), v1 - __bfloat162float(h1));
            lv.y = pack_bf2(v2 - __bfloat162float(h2), v3 - __bfloat162float(h3));
            size_t e = (((size_t)img * HH + h) * WW + w) * CI + pass * 64 + cc * 4;
            *(uint2*)(g_act_hi + e) = hv;
            *(uint2*)(g_act_lo + e) = lv;
        }
    }
}

// ---------------------------------------------------------------------------
// conv_kernel: R7 geometry (256 thr, 8 warps 4Mx2N, warp 32x64), 18 x K=64
// stages; NEW: 3-deep stage ring (192KB), cp.async issued 2 stages ahead.
// ---------------------------------------------------------------------------
#define CONV_SMEM (3 * 65536)

__global__ __launch_bounds__(256, 1)
void conv_kernel() {
    extern __shared__ char smem[];
    const u32 sb = smem_u32(smem);
    const int tid  = threadIdx.x;
    const int wid  = tid >> 5;
    const int lane = tid & 31;
    const int img  = blockIdx.x;
    const int h    = blockIdx.y;
    const int wm = wid & 3;
    const int wn = wid >> 2;
    const int qg = lane >> 2;
    const int qt = lane & 3;

    const int a_r0 = (lane & 7) + ((lane >> 3) & 1) * 8;
    const int a_cs = (lane >> 4) & 1;
    const int b_r0 = (lane & 7) + ((lane >> 4) & 1) * 8;
    const int b_cs = (lane >> 3) & 1;

    float acc[2][8][4];
#pragma unroll
    for (int i = 0; i < 2; i++)
#pragma unroll
        for (int j = 0; j < 8; j++)
#pragma unroll
            for (int c = 0; c < 4; c++) acc[i][j][c] = 0.f;

    auto issue_stage = [&](int s) {
        const int tap = s >> 1, half = s & 1;
        const int dy = tap / 3, dx = tap % 3;
        const int hsrc = h + dy - 1;
        const bool hok = (unsigned)hsrc < (unsigned)HH;
        const u32 buf = sb + (u32)(s % 3) * 65536u;
        for (int c = tid; c < 4096; c += 256) {
            const int region = c >> 10;          // 0:Ahi 1:Alo 2:Bhi 3:Blo
            const int q   = c & 1023;
            const int row = q >> 3;
            const int ch  = q & 7;
            const u32 dst = buf + (u32)region * 16384u + (u32)row * 128u
                          + (u32)((ch ^ (row & 7)) << 4);
            if (region < 2) {
                const int wsrc = row + dx - 1;
                const bool ok = hok && (unsigned)wsrc < (unsigned)WW;
                const __nv_bfloat16* base = region ? g_act_lo : g_act_hi;
                const __nv_bfloat16* src = base +
                    ((((size_t)img * HH + (ok ? hsrc : 0)) * WW
                      + (ok ? wsrc : 0)) * CI + half * 64 + ch * 8);
                CP_ASYNC16(dst, src, ok ? 16u : 0u);
            } else {
                const int tile = (tap * 2 + half) * 2 + (region - 2);
                const __nv_bfloat16* src = g_wb + (size_t)tile * 8192 + q * 8;
                CP_ASYNC16(dst, src, 16u);
            }
        }
        CP_COMMIT();
    };

    issue_stage(0);
    issue_stage(1);
    for (int s = 0; s < 18; s++) {
        if (s + 2 < 18)      { issue_stage(s + 2); CP_WAIT2(); }
        else if (s + 1 < 18) { CP_WAIT1(); }
        else                 { CP_WAIT0(); }
        __syncthreads();
        const u32 buf = sb + (u32)(s % 3) * 65536u;
        const u32 ah_b = buf, al_b = buf + 16384u;
        const u32 bh_b = buf + 32768u, bl_b = buf + 49152u;
#pragma unroll
        for (int kk = 0; kk < 4; kk++) {
            u32 Ah[2][4], Al[2][4], Bh[4][4], Bl[4][4];
#pragma unroll
            for (int i = 0; i < 2; i++) {
                const int row = wm * 32 + i * 16 + a_r0;
                const int ch  = kk * 2 + a_cs;
                const u32 off = (u32)row * 128u + (u32)((ch ^ (row & 7)) << 4);
                LDM4(Ah[i], ah_b + off);
                LDM4(Al[i], al_b + off);
            }
#pragma unroll
            for (int jj = 0; jj < 4; jj++) {
                const int row = wn * 64 + jj * 16 + b_r0;
                const int ch  = kk * 2 + b_cs;
                const u32 off = (u32)row * 128u + (u32)((ch ^ (row & 7)) << 4);
                LDM4(Bh[jj], bh_b + off);
                LDM4(Bl[jj], bl_b + off);
            }
#pragma unroll
            for (int i = 0; i < 2; i++)
#pragma unroll
                for (int j = 0; j < 8; j++) {
                    const u32 bh0 = Bh[j >> 1][(j & 1) * 2];
                    const u32 bh1 = Bh[j >> 1][(j & 1) * 2 + 1];
                    const u32 bl0 = Bl[j >> 1][(j & 1) * 2];
                    const u32 bl1 = Bl[j >> 1][(j & 1) * 2 + 1];
                    MMA16816(acc[i][j], Ah[i], bh0, bh1);
                    MMA16816(acc[i][j], Al[i], bh0, bh1);
                    MMA16816(acc[i][j], Ah[i], bl0, bl1);
                }
        }
        __syncthreads();
    }

    // ---- fused channel L2 norm epilogue (bf16 hi/lo output) ----
    float* part = (float*)smem;   // [2 wn][128 w]
#pragma unroll
    for (int i = 0; i < 2; i++)
#pragma unroll
        for (int rh = 0; rh < 2; rh++) {
            float ssum = 0.f;
#pragma unroll
            for (int j = 0; j < 8; j++) {
                float c0 = acc[i][j][rh * 2], c1 = acc[i][j][rh * 2 + 1];
                ssum = fmaf(c0, c0, fmaf(c1, c1, ssum));
            }
            ssum += __shfl_xor_sync(0xFFFFFFFFu, ssum, 1);
            ssum += __shfl_xor_sync(0xFFFFFFFFu, ssum, 2);
            if (qt == 0)
                part[wn * 128 + wm * 32 + i * 16 + rh * 8 + qg] = ssum;
        }
    __syncthreads();
#pragma unroll
    for (int i = 0; i < 2; i++)
#pragma unroll
        for (int rh = 0; rh < 2; rh++) {
            const int r = wm * 32 + i * 16 + rh * 8 + qg;
            const float inv = rsqrtf(part[r] + part[128 + r]);
            const size_t base = (((size_t)img * HH + h) * WW + r) * CO + wn * 64;
#pragma unroll
            for (int j = 0; j < 8; j++) {
                float v0 = acc[i][j][rh * 2] * inv;
                float v1 = acc[i][j][rh * 2 + 1] * inv;
                __nv_bfloat16 h0 = __float2bfloat16(v0);
                __nv_bfloat16 h1 = __float2bfloat16(v1);
                u32 hv = (u32)__bfloat16_as_ushort(h0)
                       | ((u32)__bfloat16_as_ushort(h1) << 16);
                u32 lv = pack_bf2(v0 - __bfloat162float(h0),
                                  v1 - __bfloat162float(h1));
                *(u32*)(g_nfh + base + j * 8 + qt * 2) = hv;
                *(u32*)(g_nfl + base + j * 8 + qt * 2) = lv;
            }
        }
}

// ---------------------------------------------------------------------------
// corr_kernel: R7 tensor version with 3-deep f2 ring (f2 issued 2 ahead).
// ---------------------------------------------------------------------------
#define CORR_F2OFF  65536
#define CORR_F2BUF  36864
#define CORR_OUTOFF (65536 + 3 * 36864)
#define CORR_SMEM   (65536 + 3 * 36864 + 4800)

__global__ __launch_bounds__(256, 1)
void corr_kernel(float* __restrict__ out) {
    extern __shared__ char smem[];
    const u32 sb = smem_u32(smem);
    const int tid  = threadIdx.x;
    const int wid  = tid >> 5;
    const int lane = tid & 31;
    const int h    = blockIdx.x;
    const int pb   = blockIdx.y;
    const int pair = pb >> 2, b = pb & 3;
    const int img1 = pair * 4 + b;
    const int img2 = img1 + 4;
    const int pp   = wid & 1;
    const int idx  = wid >> 1;
    const int qg = lane >> 2, qt = lane & 3;
    const int a_r0 = (lane & 7) + ((lane >> 3) & 1) * 8;
    const int a_cs = (lane >> 4) & 1;
    const int b_r0 = (lane & 7) + ((lane >> 4) & 1) * 8;
    const int b_cs = (lane >> 3) & 1;

    for (int t = tid; t < 4096; t += 256) {
        const int ch  = t & 7;
        const int row = (t >> 3) & 63;
        const int par = (t >> 9) & 1;
        const int sp  = (t >> 10) & 1;
        const int chf = (t >> 11) & 1;
        const int w   = par + 2 * row;
        const __nv_bfloat16* src = (sp ? g_nfl : g_nfh) +
            ((((size_t)img1 * HH + h) * WW + w) * CO + chf * 64 + ch * 8);
        const u32 dst = sb + (u32)((((chf * 2 + sp) * 2 + par) * 64 + row) * 128)
                      + (u32)((ch ^ (row & 7)) << 4);
        CP_ASYNC16(dst, src, 16u);
    }

    auto issue_f2 = [&](int it) {
        const int py  = it >> 1;
        const int chf = it & 1;
        const int h2  = h + 2 * py - 8;
        const bool hok = (unsigned)h2 < (unsigned)HH;
        const u32 buf = sb + CORR_F2OFF + (u32)(it % 3) * CORR_F2BUF;
        for (int t = tid; t < 2304; t += 256) {
            const int ch   = t & 7;
            const int rr   = t >> 3;
            const int row  = rr % 72;
            const int rest = rr / 72;
            const int par = rest & 1, sp = rest >> 1;
            const int w2 = par + 2 * (row - 4);
            const bool ok = hok && (unsigned)w2 < (unsigned)WW;
            const __nv_bfloat16* src = (sp ? g_nfl : g_nfh) +
                ((((size_t)img2 * HH + (ok ? h2 : 0)) * WW + (ok ? w2 : 0)) * CO
                 + chf * 64 + ch * 8);
            const u32 dst = buf + (u32)(((sp * 2 + par) * 72 + row) * 128)
                          + (u32)((ch ^ (row & 7)) << 4);
            CP_ASYNC16(dst, src, ok ? 16u : 0u);
        }
        CP_COMMIT();
    };

    issue_f2(0);                 // group 0 = f1 + f2(0)
    issue_f2(1);                 // group 1
    float acc[3][4];
    float* ost = (float*)(smem + CORR_OUTOFF);

    for (int it = 0; it < 18; it++) {
        if (it + 2 < 18)      { issue_f2(it + 2); CP_WAIT2(); }
        else if (it + 1 < 18) { CP_WAIT1(); }
        else                  { CP_WAIT0(); }
        __syncthreads();
        const int chf = it & 1;
        if (chf == 0) {
#pragma unroll
            for (int t2 = 0; t2 < 3; t2++)
#pragma unroll
                for (int c = 0; c < 4; c++) acc[t2][c] = 0.f;
        }
        const u32 f2b = sb + CORR_F2OFF + (u32)(it % 3) * CORR_F2BUF;
#pragma unroll
        for (int kk = 0; kk < 4; kk++) {
            u32 Ah[4], Al[4], Bh[6], Bl[6];
            {
                const int row = idx * 16 + a_r0;
                const int ch  = kk * 2 + a_cs;
                const u32 swz = (u32)((ch ^ (row & 7)) << 4);
                const u32 oh = sb + (u32)((((chf * 2 + 0) * 2 + pp) * 64 + row) * 128) + swz;
                const u32 ol = sb + (u32)((((chf * 2 + 1) * 2 + pp) * 64 + row) * 128) + swz;
                LDM4(Ah, oh);
                LDM4(Al, ol);
            }
            {
                const int row = idx * 16 + b_r0;
                const int ch  = kk * 2 + b_cs;
                const u32 swz = (u32)((ch ^ (row & 7)) << 4);
                const u32 oh = f2b + (u32)(((0 * 2 + pp) * 72 + row) * 128) + swz;
                const u32 ol = f2b + (u32)(((1 * 2 + pp) * 72 + row) * 128) + swz;
                LDM4(Bh, oh);
                LDM4(Bl, ol);
            }
            {
                const int row = idx * 16 + 16 + (lane & 7);
                const int ch  = kk * 2 + ((lane >> 3) & 1);
                const u32 swz = (u32)((ch ^ (row & 7)) << 4);
                const u32 oh = f2b + (u32)(((0 * 2 + pp) * 72 + row) * 128) + swz;
                const u32 ol = f2b + (u32)(((1 * 2 + pp) * 72 + row) * 128) + swz;
                LDM2(Bh + 4, oh);
                LDM2(Bl + 4, ol);
            }
#pragma unroll
            for (int t2 = 0; t2 < 3; t2++) {
                const u32 bh0 = Bh[t2 * 2], bh1 = Bh[t2 * 2 + 1];
                const u32 bl0 = Bl[t2 * 2], bl1 = Bl[t2 * 2 + 1];
                MMA16816(acc[t2], Ah, bh0, bh1);
                MMA16816(acc[t2], Al, bh0, bh1);
                MMA16816(acc[t2], Ah, bl0, bl1);
            }
        }
        if (chf == 1) {
            const int py = it >> 1;
#pragma unroll
            for (int t2 = 0; t2 < 3; t2++)
#pragma unroll
                for (int reg = 0; reg < 4; reg++) {
                    const int r  = qg + 8 * (reg >> 1);
                    const int j  = 8 * t2 + 2 * qt + (reg & 1);
                    const int px = j - r;
                    if ((unsigned)px <= 8u) {
                        const int w = pp + 2 * (16 * idx + r);
                        ost[px * 132 + w] = acc[t2][reg];
                    }
                }
            __syncthreads();
            for (int t2 = tid; t2 < 1152; t2 += 256) {
                const int px = t2 >> 7;
                const int w  = t2 & 127;
                out[(((size_t)b * 243 + pair * 81 + py * 9 + px) * HH + h) * WW + w]
                    = ost[px * 132 + w];
            }
        }
        __syncthreads();
    }
}

// ---------------------------------------------------------------------------
extern "C" void kernel_launch(void* const* d_in, const int* in_sizes, int n_in,
                              void* d_out, int out_size) {
    const float* x     = (const float*)d_in[0];
    const float* gamma = (const float*)d_in[1];
    const float* beta  = (const float*)d_in[2];
    const float* mean  = (const float*)d_in[3];
    const float* var   = (const float*)d_in[4];
    const float* convw = (const float*)d_in[5];
    float* out = (float*)d_out;

    cudaFuncSetAttribute(conv_kernel,
                         cudaFuncAttributeMaxDynamicSharedMemorySize, CONV_SMEM);
    cudaFuncSetAttribute(corr_kernel,
                         cudaFuncAttributeMaxDynamicSharedMemorySize, CORR_SMEM);

    prep_bn_kernel<<<1, 128>>>(gamma, beta, mean, var);
    prep_w_kernel<<<36, 256>>>(convw);
    act_split_kernel<<<dim3(NIMG, HH), 256>>>(x);
    conv_kernel<<<dim3(NIMG, HH), 256, CONV_SMEM>>>();
    corr_kernel<<<dim3(HH, 3 * BB), 256, CORR_SMEM>>>(out);
}

// round 13
// speedup vs baseline: 1.0317x; 1.0001x over previous
#include <cuda_runtime.h>
#include <cuda_bf16.h>
#include <cstdint>

// ---------------------------------------------------------------------------
// CorrelationModule on sm_100 (base target -- NO tcgen05, NO f32x2):
//   BN+ReLU -> conv3x3 as mma.sync bf16 split-precision implicit GEMM
//   (R7 geometry, 3-deep cp.async ring, REGISTER-DOUBLE-BUFFERED fragments)
//   -> fused channel L2 norm (bf16 hi/lo)
//   -> 9x9 dilated correlation on mma.sync (parity Toeplitz, 3-deep ring).
// ---------------------------------------------------------------------------

#define BB    4
#define GG    4
#define CI    128
#define CO    128
#define HH    64
#define WW    128
#define NIMG  16
#define PATCH 9
#define PADC  8

typedef unsigned int u32;

// ------------------------------ device scratch -----------------------------
__device__ __align__(128) __nv_bfloat16  g_nfh[NIMG * HH * WW * CO];     // 32 MB
__device__ __align__(128) __nv_bfloat16  g_nfl[NIMG * HH * WW * CO];     // 32 MB
__device__ __align__(128) __nv_bfloat16  g_act_hi[NIMG * HH * WW * CI];  // 32 MB
__device__ __align__(128) __nv_bfloat16  g_act_lo[NIMG * HH * WW * CI];  // 32 MB
__device__ __align__(128) __nv_bfloat16  g_wb[36 * 128 * 64];
__device__ float g_bn_a[CI];
__device__ float g_bn_b[CI];

// ------------------------------ helpers ------------------------------------
__device__ __forceinline__ u32 smem_u32(const void* p) {
    u32 a;
    asm("{ .reg .u64 t; cvta.to.shared.u64 t, %1; cvt.u32.u64 %0, t; }"
        : "=r"(a) : "l"(p));
    return a;
}

#define LDM4(r, addr) \
    asm volatile("ldmatrix.sync.aligned.m8n8.x4.shared.b16 {%0,%1,%2,%3}, [%4];" \
        : "=r"((r)[0]), "=r"((r)[1]), "=r"((r)[2]), "=r"((r)[3]) : "r"(addr))
#define LDM2(r, addr) \
    asm volatile("ldmatrix.sync.aligned.m8n8.x2.shared.b16 {%0,%1}, [%2];" \
        : "=r"((r)[0]), "=r"((r)[1]) : "r"(addr))

#define MMA16816(d, a, b0_, b1_) \
    asm volatile("mma.sync.aligned.m16n8k16.row.col.f32.bf16.bf16.f32 " \
        "{%0,%1,%2,%3}, {%4,%5,%6,%7}, {%8,%9}, {%0,%1,%2,%3};" \
        : "+f"((d)[0]), "+f"((d)[1]), "+f"((d)[2]), "+f"((d)[3]) \
        : "r"((a)[0]), "r"((a)[1]), "r"((a)[2]), "r"((a)[3]), "r"(b0_), "r"(b1_))

#define CP_ASYNC16(dst, src, sz) \
    asm volatile("cp.async.cg.shared.global [%0], [%1], 16, %2;" \
                 :: "r"(dst), "l"(src), "r"(sz) : "memory")
#define CP_COMMIT() asm volatile("cp.async.commit_group;" ::: "memory")
#define CP_WAIT2()  asm volatile("cp.async.wait_group 2;" ::: "memory")
#define CP_WAIT1()  asm volatile("cp.async.wait_group 1;" ::: "memory")
#define CP_WAIT0()  asm volatile("cp.async.wait_group 0;" ::: "memory")

__device__ __forceinline__ u32 pack_bf2(float a, float b) {
    __nv_bfloat16 x = __float2bfloat16(a), y = __float2bfloat16(b);
    return (u32)__bfloat16_as_ushort(x) | ((u32)__bfloat16_as_ushort(y) << 16);
}

// ---------------------------------------------------------------------------
__global__ void prep_bn_kernel(const float* __restrict__ gamma,
                               const float* __restrict__ beta,
                               const float* __restrict__ mean,
                               const float* __restrict__ var) {
    int c = threadIdx.x;
    if (c < CI) {
        float a = gamma[c] * rsqrtf(var[c] + 1e-5f);
        g_bn_a[c] = a;
        g_bn_b[c] = beta[c] - mean[c] * a;
    }
}

// ---------------------------------------------------------------------------
__global__ void prep_w_kernel(const float* __restrict__ convw) {
    int im   = blockIdx.x;              // 0..35
    int sp   = im & 1;
    int half = (im >> 1) & 1;
    int tap  = im >> 2;
    int dy = tap / 3, dx = tap % 3;
    __nv_bfloat16* base = g_wb + (size_t)im * 8192;
    for (int t = threadIdx.x; t < 128 * 64; t += 256) {
        int cout = t >> 6;
        int cl   = t & 63;
        int cin  = half * 64 + cl;
        float wv = convw[(cout * CI + cin) * 9 + dy * 3 + dx];
        __nv_bfloat16 hi = __float2bfloat16(wv);
        base[t] = (sp == 0) ? hi : __float2bfloat16(wv - __bfloat162float(hi));
    }
}

// ---------------------------------------------------------------------------
__global__ __launch_bounds__(256)
void act_split_kernel(const float* __restrict__ x) {
    const int img = blockIdx.x, h = blockIdx.y;
    const int g = img >> 2, b = img & 3;
    __shared__ float s[64 * 133];
    const int tid = threadIdx.x;
    const int c2 = tid >> 7;
    const int wl = tid & 127;

    for (int pass = 0; pass < 2; pass++) {
        __syncthreads();
        for (int co = 0; co < 64; co += 2) {
            int cl  = co + c2;
            int cin = pass * 64 + cl;
            float xv = x[(((size_t)b * 512 + g * 128 + cin) * HH + h) * WW + wl];
            s[cl * 133 + wl] = fmaxf(fmaf(xv, g_bn_a[cin], g_bn_b[cin]), 0.f);
        }
        __syncthreads();
        for (int t = tid; t < 2048; t += 256) {
            int w  = t >> 4;
            int cc = t & 15;
            float v0 = s[(cc * 4 + 0) * 133 + w];
            float v1 = s[(cc * 4 + 1) * 133 + w];
            float v2 = s[(cc * 4 + 2) * 133 + w];
            float v3 = s[(cc * 4 + 3) * 133 + w];
            __nv_bfloat16 h0 = __float2bfloat16(v0), h1 = __float2bfloat16(v1);
            __nv_bfloat16 h2 = __float2bfloat16(v2), h3 = __float2bfloat16(v3);
            uint2 hv, lv;
            hv.x = (u32)__bfloat16_as_ushort(h0) | ((u32)__bfloat16_as_ushort(h1) << 16);
            hv.y = (u32)__bfloat16_as_ushort(h2) | ((u32)__bfloat16_as_ushort(h3) << 16);
            lv.x = pack_bf2(v0 - __bfloat162float(h0), v1 - __bfloat162float(h1));
            lv.y = pack_bf2(v2 - __bfloat162float(h2), v3 - __bfloat162float(h3));
            size_t e = (((size_t)img * HH + h) * WW + w) * CI + pass * 64 + cc * 4;
            *(uint2*)(g_act_hi + e) = hv;
            *(uint2*)(g_act_lo + e) = lv;
        }
    }
}

// ---------------------------------------------------------------------------
// conv_kernel: R7 geometry (256 thr, 8 warps 4Mx2N, warp 32x64), 18 x K=64
// stages, 3-deep cp.async ring; kk-loop software pipeline with
// double-buffered ldmatrix fragments (load kk+1 while MMAing kk).
// ---------------------------------------------------------------------------
#define CONV_SMEM (3 * 65536)

__global__ __launch_bounds__(256, 1)
void conv_kernel() {
    extern __shared__ char smem[];
    const u32 sb = smem_u32(smem);
    const int tid  = threadIdx.x;
    const int wid  = tid >> 5;
    const int lane = tid & 31;
    const int img  = blockIdx.x;
    const int h    = blockIdx.y;
    const int wm = wid & 3;
    const int wn = wid >> 2;
    const int qg = lane >> 2;
    const int qt = lane & 3;

    const int a_r0 = (lane & 7) + ((lane >> 3) & 1) * 8;
    const int a_cs = (lane >> 4) & 1;
    const int b_r0 = (lane & 7) + ((lane >> 4) & 1) * 8;
    const int b_cs = (lane >> 3) & 1;

    float acc[2][8][4];
#pragma unroll
    for (int i = 0; i < 2; i++)
#pragma unroll
        for (int j = 0; j < 8; j++)
#pragma unroll
            for (int c = 0; c < 4; c++) acc[i][j][c] = 0.f;

    auto issue_stage = [&](int s) {
        const int tap = s >> 1, half = s & 1;
        const int dy = tap / 3, dx = tap % 3;
        const int hsrc = h + dy - 1;
        const bool hok = (unsigned)hsrc < (unsigned)HH;
        const u32 buf = sb + (u32)(s % 3) * 65536u;
        for (int c = tid; c < 4096; c += 256) {
            const int region = c >> 10;          // 0:Ahi 1:Alo 2:Bhi 3:Blo
            const int q   = c & 1023;
            const int row = q >> 3;
            const int ch  = q & 7;
            const u32 dst = buf + (u32)region * 16384u + (u32)row * 128u
                          + (u32)((ch ^ (row & 7)) << 4);
            if (region < 2) {
                const int wsrc = row + dx - 1;
                const bool ok = hok && (unsigned)wsrc < (unsigned)WW;
                const __nv_bfloat16* base = region ? g_act_lo : g_act_hi;
                const __nv_bfloat16* src = base +
                    ((((size_t)img * HH + (ok ? hsrc : 0)) * WW
                      + (ok ? wsrc : 0)) * CI + half * 64 + ch * 8);
                CP_ASYNC16(dst, src, ok ? 16u : 0u);
            } else {
                const int tile = (tap * 2 + half) * 2 + (region - 2);
                const __nv_bfloat16* src = g_wb + (size_t)tile * 8192 + q * 8;
                CP_ASYNC16(dst, src, 16u);
            }
        }
        CP_COMMIT();
    };

    // double-buffered fragments: [buf][...]
    u32 Ahf[2][2][4], Alf[2][2][4], Bhf[2][4][4], Blf[2][4][4];

    issue_stage(0);
    issue_stage(1);
    for (int s = 0; s < 18; s++) {
        if (s + 2 < 18)      { issue_stage(s + 2); CP_WAIT2(); }
        else if (s + 1 < 18) { CP_WAIT1(); }
        else                 { CP_WAIT0(); }
        __syncthreads();
        const u32 buf = sb + (u32)(s % 3) * 65536u;
        const u32 ah_b = buf, al_b = buf + 16384u;
        const u32 bh_b = buf + 32768u, bl_b = buf + 49152u;

        auto load_k = [&](int kk, int bsel) {
#pragma unroll
            for (int i = 0; i < 2; i++) {
                const int row = wm * 32 + i * 16 + a_r0;
                const int ch  = kk * 2 + a_cs;
                const u32 off = (u32)row * 128u + (u32)((ch ^ (row & 7)) << 4);
                LDM4(Ahf[bsel][i], ah_b + off);
                LDM4(Alf[bsel][i], al_b + off);
            }
#pragma unroll
            for (int jj = 0; jj < 4; jj++) {
                const int row = wn * 64 + jj * 16 + b_r0;
                const int ch  = kk * 2 + b_cs;
                const u32 off = (u32)row * 128u + (u32)((ch ^ (row & 7)) << 4);
                LDM4(Bhf[bsel][jj], bh_b + off);
                LDM4(Blf[bsel][jj], bl_b + off);
            }
        };

        load_k(0, 0);
#pragma unroll
        for (int kk = 0; kk < 4; kk++) {
            const int cur = kk & 1;
            if (kk < 3) load_k(kk + 1, cur ^ 1);
#pragma unroll
            for (int i = 0; i < 2; i++)
#pragma unroll
                for (int j = 0; j < 8; j++) {
                    const u32 bh0 = Bhf[cur][j >> 1][(j & 1) * 2];
                    const u32 bh1 = Bhf[cur][j >> 1][(j & 1) * 2 + 1];
                    const u32 bl0 = Blf[cur][j >> 1][(j & 1) * 2];
                    const u32 bl1 = Blf[cur][j >> 1][(j & 1) * 2 + 1];
                    MMA16816(acc[i][j], Ahf[cur][i], bh0, bh1);
                    MMA16816(acc[i][j], Alf[cur][i], bh0, bh1);
                    MMA16816(acc[i][j], Ahf[cur][i], bl0, bl1);
                }
        }
        __syncthreads();
    }

    // ---- fused channel L2 norm epilogue (bf16 hi/lo output) ----
    float* part = (float*)smem;   // [2 wn][128 w]
#pragma unroll
    for (int i = 0; i < 2; i++)
#pragma unroll
        for (int rh = 0; rh < 2; rh++) {
            float ssum = 0.f;
#pragma unroll
            for (int j = 0; j < 8; j++) {
                float c0 = acc[i][j][rh * 2], c1 = acc[i][j][rh * 2 + 1];
                ssum = fmaf(c0, c0, fmaf(c1, c1, ssum));
            }
            ssum += __shfl_xor_sync(0xFFFFFFFFu, ssum, 1);
            ssum += __shfl_xor_sync(0xFFFFFFFFu, ssum, 2);
            if (qt == 0)
                part[wn * 128 + wm * 32 + i * 16 + rh * 8 + qg] = ssum;
        }
    __syncthreads();
#pragma unroll
    for (int i = 0; i < 2; i++)
#pragma unroll
        for (int rh = 0; rh < 2; rh++) {
            const int r = wm * 32 + i * 16 + rh * 8 + qg;
            const float inv = rsqrtf(part[r] + part[128 + r]);
            const size_t base = (((size_t)img * HH + h) * WW + r) * CO + wn * 64;
#pragma unroll
            for (int j = 0; j < 8; j++) {
                float v0 = acc[i][j][rh * 2] * inv;
                float v1 = acc[i][j][rh * 2 + 1] * inv;
                __nv_bfloat16 h0 = __float2bfloat16(v0);
                __nv_bfloat16 h1 = __float2bfloat16(v1);
                u32 hv = (u32)__bfloat16_as_ushort(h0)
                       | ((u32)__bfloat16_as_ushort(h1) << 16);
                u32 lv = pack_bf2(v0 - __bfloat162float(h0),
                                  v1 - __bfloat162float(h1));
                *(u32*)(g_nfh + base + j * 8 + qt * 2) = hv;
                *(u32*)(g_nfl + base + j * 8 + qt * 2) = lv;
            }
        }
}

// ---------------------------------------------------------------------------
// corr_kernel: R11-passing tensor version (3-deep f2 ring), unchanged.
// ---------------------------------------------------------------------------
#define CORR_F2OFF  65536
#define CORR_F2BUF  36864
#define CORR_OUTOFF (65536 + 3 * 36864)
#define CORR_SMEM   (65536 + 3 * 36864 + 4800)

__global__ __launch_bounds__(256, 1)
void corr_kernel(float* __restrict__ out) {
    extern __shared__ char smem[];
    const u32 sb = smem_u32(smem);
    const int tid  = threadIdx.x;
    const int wid  = tid >> 5;
    const int lane = tid & 31;
    const int h    = blockIdx.x;
    const int pb   = blockIdx.y;
    const int pair = pb >> 2, b = pb & 3;
    const int img1 = pair * 4 + b;
    const int img2 = img1 + 4;
    const int pp   = wid & 1;
    const int idx  = wid >> 1;
    const int qg = lane >> 2, qt = lane & 3;
    const int a_r0 = (lane & 7) + ((lane >> 3) & 1) * 8;
    const int a_cs = (lane >> 4) & 1;
    const int b_r0 = (lane & 7) + ((lane >> 4) & 1) * 8;
    const int b_cs = (lane >> 3) & 1;

    for (int t = tid; t < 4096; t += 256) {
        const int ch  = t & 7;
        const int row = (t >> 3) & 63;
        const int par = (t >> 9) & 1;
        const int sp  = (t >> 10) & 1;
        const int chf = (t >> 11) & 1;
        const int w   = par + 2 * row;
        const __nv_bfloat16* src = (sp ? g_nfl : g_nfh) +
            ((((size_t)img1 * HH + h) * WW + w) * CO + chf * 64 + ch * 8);
        const u32 dst = sb + (u32)((((chf * 2 + sp) * 2 + par) * 64 + row) * 128)
                      + (u32)((ch ^ (row & 7)) << 4);
        CP_ASYNC16(dst, src, 16u);
    }

    auto issue_f2 = [&](int it) {
        const int py  = it >> 1;
        const int chf = it & 1;
        const int h2  = h + 2 * py - 8;
        const bool hok = (unsigned)h2 < (unsigned)HH;
        const u32 buf = sb + CORR_F2OFF + (u32)(it % 3) * CORR_F2BUF;
        for (int t = tid; t < 2304; t += 256) {
            const int ch   = t & 7;
            const int rr   = t >> 3;
            const int row  = rr % 72;
            const int rest = rr / 72;
            const int par = rest & 1, sp = rest >> 1;
            const int w2 = par + 2 * (row - 4);
            const bool ok = hok && (unsigned)w2 < (unsigned)WW;
            const __nv_bfloat16* src = (sp ? g_nfl : g_nfh) +
                ((((size_t)img2 * HH + (ok ? h2 : 0)) * WW + (ok ? w2 : 0)) * CO
                 + chf * 64 + ch * 8);
            const u32 dst = buf + (u32)(((sp * 2 + par) * 72 + row) * 128)
                          + (u32)((ch ^ (row & 7)) << 4);
            CP_ASYNC16(dst, src, ok ? 16u : 0u);
        }
        CP_COMMIT();
    };

    issue_f2(0);                 // group 0 = f1 + f2(0)
    issue_f2(1);                 // group 1
    float acc[3][4];
    float* ost = (float*)(smem + CORR_OUTOFF);

    for (int it = 0; it < 18; it++) {
        if (it + 2 < 18)      { issue_f2(it + 2); CP_WAIT2(); }
        else if (it + 1 < 18) { CP_WAIT1(); }
        else                  { CP_WAIT0(); }
        __syncthreads();
        const int chf = it & 1;
        if (chf == 0) {
#pragma unroll
            for (int t2 = 0; t2 < 3; t2++)
#pragma unroll
                for (int c = 0; c < 4; c++) acc[t2][c] = 0.f;
        }
        const u32 f2b = sb + CORR_F2OFF + (u32)(it % 3) * CORR_F2BUF;
#pragma unroll
        for (int kk = 0; kk < 4; kk++) {
            u32 Ah[4], Al[4], Bh[6], Bl[6];
            {
                const int row = idx * 16 + a_r0;
                const int ch  = kk * 2 + a_cs;
                const u32 swz = (u32)((ch ^ (row & 7)) << 4);
                const u32 oh = sb + (u32)((((chf * 2 + 0) * 2 + pp) * 64 + row) * 128) + swz;
                const u32 ol = sb + (u32)((((chf * 2 + 1) * 2 + pp) * 64 + row) * 128) + swz;
                LDM4(Ah, oh);
                LDM4(Al, ol);
            }
            {
                const int row = idx * 16 + b_r0;
                const int ch  = kk * 2 + b_cs;
                const u32 swz = (u32)((ch ^ (row & 7)) << 4);
                const u32 oh = f2b + (u32)(((0 * 2 + pp) * 72 + row) * 128) + swz;
                const u32 ol = f2b + (u32)(((1 * 2 + pp) * 72 + row) * 128) + swz;
                LDM4(Bh, oh);
                LDM4(Bl, ol);
            }
            {
                const int row = idx * 16 + 16 + (lane & 7);
                const int ch  = kk * 2 + ((lane >> 3) & 1);
                const u32 swz = (u32)((ch ^ (row & 7)) << 4);
                const u32 oh = f2b + (u32)(((0 * 2 + pp) * 72 + row) * 128) + swz;
                const u32 ol = f2b + (u32)(((1 * 2 + pp) * 72 + row) * 128) + swz;
                LDM2(Bh + 4, oh);
                LDM2(Bl + 4, ol);
            }
#pragma unroll
            for (int t2 = 0; t2 < 3; t2++) {
                const u32 bh0 = Bh[t2 * 2], bh1 = Bh[t2 * 2 + 1];
                const u32 bl0 = Bl[t2 * 2], bl1 = Bl[t2 * 2 + 1];
                MMA16816(acc[t2], Ah, bh0, bh1);
                MMA16816(acc[t2], Al, bh0, bh1);
                MMA16816(acc[t2], Ah, bl0, bl1);
            }
        }
        if (chf == 1) {
            const int py = it >> 1;
#pragma unroll
            for (int t2 = 0; t2 < 3; t2++)
#pragma unroll
                for (int reg = 0; reg < 4; reg++) {
                    const int r  = qg + 8 * (reg >> 1);
                    const int j  = 8 * t2 + 2 * qt + (reg & 1);
                    const int px = j - r;
                    if ((unsigned)px <= 8u) {
                        const int w = pp + 2 * (16 * idx + r);
                        ost[px * 132 + w] = acc[t2][reg];
                    }
                }
            __syncthreads();
            for (int t2 = tid; t2 < 1152; t2 += 256) {
                const int px = t2 >> 7;
                const int w  = t2 & 127;
                out[(((size_t)b * 243 + pair * 81 + py * 9 + px) * HH + h) * WW + w]
                    = ost[px * 132 + w];
            }
        }
        __syncthreads();
    }
}

// ---------------------------------------------------------------------------
extern "C" void kernel_launch(void* const* d_in, const int* in_sizes, int n_in,
                              void* d_out, int out_size) {
    const float* x     = (const float*)d_in[0];
    const float* gamma = (const float*)d_in[1];
    const float* beta  = (const float*)d_in[2];
    const float* mean  = (const float*)d_in[3];
    const float* var   = (const float*)d_in[4];
    const float* convw = (const float*)d_in[5];
    float* out = (float*)d_out;

    cudaFuncSetAttribute(conv_kernel,
                         cudaFuncAttributeMaxDynamicSharedMemorySize, CONV_SMEM);
    cudaFuncSetAttribute(corr_kernel,
                         cudaFuncAttributeMaxDynamicSharedMemorySize, CORR_SMEM);

    prep_bn_kernel<<<1, 128>>>(gamma, beta, mean, var);
    prep_w_kernel<<<36, 256>>>(convw);
    act_split_kernel<<<dim3(NIMG, HH), 256>>>(x);
    conv_kernel<<<dim3(NIMG, HH), 256, CONV_SMEM>>>();
    corr_kernel<<<dim3(HH, 3 * BB), 256, CORR_SMEM>>>(out);
}

// round 14
// speedup vs baseline: 1.1013x; 1.0675x over previous
#include <cuda_runtime.h>
#include <cuda_bf16.h>
#include <cstdint>

// ---------------------------------------------------------------------------
// CorrelationModule on sm_100 (base target -- NO tcgen05, NO f32x2):
//   BN+ReLU -> conv3x3 as mma.sync bf16 split-precision implicit GEMM
//   (exact R7 best-measured body) -> fused channel L2 norm (bf16 hi/lo)
//   -> 9x9 dilated correlation on mma.sync, sp-split stages, 107KB smem
//   -> 2 CTAs/SM for cross-CTA latency hiding.
// ---------------------------------------------------------------------------

#define BB    4
#define GG    4
#define CI    128
#define CO    128
#define HH    64
#define WW    128
#define NIMG  16
#define PATCH 9
#define PADC  8

typedef unsigned int u32;

// ------------------------------ device scratch -----------------------------
__device__ __align__(128) __nv_bfloat16  g_nfh[NIMG * HH * WW * CO];     // 32 MB
__device__ __align__(128) __nv_bfloat16  g_nfl[NIMG * HH * WW * CO];     // 32 MB
__device__ __align__(128) __nv_bfloat16  g_act_hi[NIMG * HH * WW * CI];  // 32 MB
__device__ __align__(128) __nv_bfloat16  g_act_lo[NIMG * HH * WW * CI];  // 32 MB
__device__ __align__(128) __nv_bfloat16  g_wb[36 * 128 * 64];
__device__ float g_bn_a[CI];
__device__ float g_bn_b[CI];

// ------------------------------ helpers ------------------------------------
__device__ __forceinline__ u32 smem_u32(const void* p) {
    u32 a;
    asm("{ .reg .u64 t; cvta.to.shared.u64 t, %1; cvt.u32.u64 %0, t; }"
        : "=r"(a) : "l"(p));
    return a;
}

#define LDM4(r, addr) \
    asm volatile("ldmatrix.sync.aligned.m8n8.x4.shared.b16 {%0,%1,%2,%3}, [%4];" \
        : "=r"((r)[0]), "=r"((r)[1]), "=r"((r)[2]), "=r"((r)[3]) : "r"(addr))
#define LDM2(r, addr) \
    asm volatile("ldmatrix.sync.aligned.m8n8.x2.shared.b16 {%0,%1}, [%2];" \
        : "=r"((r)[0]), "=r"((r)[1]) : "r"(addr))

#define MMA16816(d, a, b0_, b1_) \
    asm volatile("mma.sync.aligned.m16n8k16.row.col.f32.bf16.bf16.f32 " \
        "{%0,%1,%2,%3}, {%4,%5,%6,%7}, {%8,%9}, {%0,%1,%2,%3};" \
        : "+f"((d)[0]), "+f"((d)[1]), "+f"((d)[2]), "+f"((d)[3]) \
        : "r"((a)[0]), "r"((a)[1]), "r"((a)[2]), "r"((a)[3]), "r"(b0_), "r"(b1_))

#define CP_ASYNC16(dst, src, sz) \
    asm volatile("cp.async.cg.shared.global [%0], [%1], 16, %2;" \
                 :: "r"(dst), "l"(src), "r"(sz) : "memory")
#define CP_COMMIT() asm volatile("cp.async.commit_group;" ::: "memory")
#define CP_WAIT1()  asm volatile("cp.async.wait_group 1;" ::: "memory")
#define CP_WAIT0()  asm volatile("cp.async.wait_group 0;" ::: "memory")

__device__ __forceinline__ u32 pack_bf2(float a, float b) {
    __nv_bfloat16 x = __float2bfloat16(a), y = __float2bfloat16(b);
    return (u32)__bfloat16_as_ushort(x) | ((u32)__bfloat16_as_ushort(y) << 16);
}

// ---------------------------------------------------------------------------
__global__ void prep_bn_kernel(const float* __restrict__ gamma,
                               const float* __restrict__ beta,
                               const float* __restrict__ mean,
                               const float* __restrict__ var) {
    int c = threadIdx.x;
    if (c < CI) {
        float a = gamma[c] * rsqrtf(var[c] + 1e-5f);
        g_bn_a[c] = a;
        g_bn_b[c] = beta[c] - mean[c] * a;
    }
}

// ---------------------------------------------------------------------------
__global__ void prep_w_kernel(const float* __restrict__ convw) {
    int im   = blockIdx.x;              // 0..35
    int sp   = im & 1;
    int half = (im >> 1) & 1;
    int tap  = im >> 2;
    int dy = tap / 3, dx = tap % 3;
    __nv_bfloat16* base = g_wb + (size_t)im * 8192;
    for (int t = threadIdx.x; t < 128 * 64; t += 256) {
        int cout = t >> 6;
        int cl   = t & 63;
        int cin  = half * 64 + cl;
        float wv = convw[(cout * CI + cin) * 9 + dy * 3 + dx];
        __nv_bfloat16 hi = __float2bfloat16(wv);
        base[t] = (sp == 0) ? hi : __float2bfloat16(wv - __bfloat162float(hi));
    }
}

// ---------------------------------------------------------------------------
__global__ __launch_bounds__(256)
void act_split_kernel(const float* __restrict__ x) {
    const int img = blockIdx.x, h = blockIdx.y;
    const int g = img >> 2, b = img & 3;
    __shared__ float s[64 * 133];
    const int tid = threadIdx.x;
    const int c2 = tid >> 7;
    const int wl = tid & 127;

    for (int pass = 0; pass < 2; pass++) {
        __syncthreads();
        for (int co = 0; co < 64; co += 2) {
            int cl  = co + c2;
            int cin = pass * 64 + cl;
            float xv = x[(((size_t)b * 512 + g * 128 + cin) * HH + h) * WW + wl];
            s[cl * 133 + wl] = fmaxf(fmaf(xv, g_bn_a[cin], g_bn_b[cin]), 0.f);
        }
        __syncthreads();
        for (int t = tid; t < 2048; t += 256) {
            int w  = t >> 4;
            int cc = t & 15;
            float v0 = s[(cc * 4 + 0) * 133 + w];
            float v1 = s[(cc * 4 + 1) * 133 + w];
            float v2 = s[(cc * 4 + 2) * 133 + w];
            float v3 = s[(cc * 4 + 3) * 133 + w];
            __nv_bfloat16 h0 = __float2bfloat16(v0), h1 = __float2bfloat16(v1);
            __nv_bfloat16 h2 = __float2bfloat16(v2), h3 = __float2bfloat16(v3);
            uint2 hv, lv;
            hv.x = (u32)__bfloat16_as_ushort(h0) | ((u32)__bfloat16_as_ushort(h1) << 16);
            hv.y = (u32)__bfloat16_as_ushort(h2) | ((u32)__bfloat16_as_ushort(h3) << 16);
            lv.x = pack_bf2(v0 - __bfloat162float(h0), v1 - __bfloat162float(h1));
            lv.y = pack_bf2(v2 - __bfloat162float(h2), v3 - __bfloat162float(h3));
            size_t e = (((size_t)img * HH + h) * WW + w) * CI + pass * 64 + cc * 4;
            *(uint2*)(g_act_hi + e) = hv;
            *(uint2*)(g_act_lo + e) = lv;
        }
    }
}

// ---------------------------------------------------------------------------
// conv_kernel: exact R7 best-measured body (256 thr, 8 warps 4Mx2N,
// warp 32x64, 18 x K=64 stages, 2-deep cp.async double buffer).
// ---------------------------------------------------------------------------
#define CONV_SMEM (2 * 65536)

__global__ __launch_bounds__(256, 1)
void conv_kernel() {
    extern __shared__ char smem[];
    const u32 sb = smem_u32(smem);
    const int tid  = threadIdx.x;
    const int wid  = tid >> 5;
    const int lane = tid & 31;
    const int img  = blockIdx.x;
    const int h    = blockIdx.y;
    const int wm = wid & 3;
    const int wn = wid >> 2;
    const int qg = lane >> 2;
    const int qt = lane & 3;

    const int a_r0 = (lane & 7) + ((lane >> 3) & 1) * 8;
    const int a_cs = (lane >> 4) & 1;
    const int b_r0 = (lane & 7) + ((lane >> 4) & 1) * 8;
    const int b_cs = (lane >> 3) & 1;

    float acc[2][8][4];
#pragma unroll
    for (int i = 0; i < 2; i++)
#pragma unroll
        for (int j = 0; j < 8; j++)
#pragma unroll
            for (int c = 0; c < 4; c++) acc[i][j][c] = 0.f;

    auto issue_stage = [&](int s) {
        const int tap = s >> 1, half = s & 1;
        const int dy = tap / 3, dx = tap % 3;
        const int hsrc = h + dy - 1;
        const bool hok = (unsigned)hsrc < (unsigned)HH;
        const u32 buf = sb + (u32)(s & 1) * 65536u;
        for (int c = tid; c < 4096; c += 256) {
            const int region = c >> 10;
            const int q   = c & 1023;
            const int row = q >> 3;
            const int ch  = q & 7;
            const u32 dst = buf + (u32)region * 16384u + (u32)row * 128u
                          + (u32)((ch ^ (row & 7)) << 4);
            if (region < 2) {
                const int wsrc = row + dx - 1;
                const bool ok = hok && (unsigned)wsrc < (unsigned)WW;
                const __nv_bfloat16* base = region ? g_act_lo : g_act_hi;
                const __nv_bfloat16* src = base +
                    ((((size_t)img * HH + (ok ? hsrc : 0)) * WW
                      + (ok ? wsrc : 0)) * CI + half * 64 + ch * 8);
                CP_ASYNC16(dst, src, ok ? 16u : 0u);
            } else {
                const int tile = (tap * 2 + half) * 2 + (region - 2);
                const __nv_bfloat16* src = g_wb + (size_t)tile * 8192 + q * 8;
                CP_ASYNC16(dst, src, 16u);
            }
        }
        CP_COMMIT();
    };

    issue_stage(0);
    for (int s = 0; s < 18; s++) {
        if (s + 1 < 18) { issue_stage(s + 1); CP_WAIT1(); }
        else            { CP_WAIT0(); }
        __syncthreads();
        const u32 buf = sb + (u32)(s & 1) * 65536u;
        const u32 ah_b = buf, al_b = buf + 16384u;
        const u32 bh_b = buf + 32768u, bl_b = buf + 49152u;
#pragma unroll
        for (int kk = 0; kk < 4; kk++) {
            u32 Ah[2][4], Al[2][4], Bh[4][4], Bl[4][4];
#pragma unroll
            for (int i = 0; i < 2; i++) {
                const int row = wm * 32 + i * 16 + a_r0;
                const int ch  = kk * 2 + a_cs;
                const u32 off = (u32)row * 128u + (u32)((ch ^ (row & 7)) << 4);
                LDM4(Ah[i], ah_b + off);
                LDM4(Al[i], al_b + off);
            }
#pragma unroll
            for (int jj = 0; jj < 4; jj++) {
                const int row = wn * 64 + jj * 16 + b_r0;
                const int ch  = kk * 2 + b_cs;
                const u32 off = (u32)row * 128u + (u32)((ch ^ (row & 7)) << 4);
                LDM4(Bh[jj], bh_b + off);
                LDM4(Bl[jj], bl_b + off);
            }
#pragma unroll
            for (int i = 0; i < 2; i++)
#pragma unroll
                for (int j = 0; j < 8; j++) {
                    const u32 bh0 = Bh[j >> 1][(j & 1) * 2];
                    const u32 bh1 = Bh[j >> 1][(j & 1) * 2 + 1];
                    const u32 bl0 = Bl[j >> 1][(j & 1) * 2];
                    const u32 bl1 = Bl[j >> 1][(j & 1) * 2 + 1];
                    MMA16816(acc[i][j], Ah[i], bh0, bh1);
                    MMA16816(acc[i][j], Al[i], bh0, bh1);
                    MMA16816(acc[i][j], Ah[i], bl0, bl1);
                }
        }
        __syncthreads();
    }

    // ---- fused channel L2 norm epilogue (bf16 hi/lo output) ----
    float* part = (float*)smem;
#pragma unroll
    for (int i = 0; i < 2; i++)
#pragma unroll
        for (int rh = 0; rh < 2; rh++) {
            float ssum = 0.f;
#pragma unroll
            for (int j = 0; j < 8; j++) {
                float c0 = acc[i][j][rh * 2], c1 = acc[i][j][rh * 2 + 1];
                ssum = fmaf(c0, c0, fmaf(c1, c1, ssum));
            }
            ssum += __shfl_xor_sync(0xFFFFFFFFu, ssum, 1);
            ssum += __shfl_xor_sync(0xFFFFFFFFu, ssum, 2);
            if (qt == 0)
                part[wn * 128 + wm * 32 + i * 16 + rh * 8 + qg] = ssum;
        }
    __syncthreads();
#pragma unroll
    for (int i = 0; i < 2; i++)
#pragma unroll
        for (int rh = 0; rh < 2; rh++) {
            const int r = wm * 32 + i * 16 + rh * 8 + qg;
            const float inv = rsqrtf(part[r] + part[128 + r]);
            const size_t base = (((size_t)img * HH + h) * WW + r) * CO + wn * 64;
#pragma unroll
            for (int j = 0; j < 8; j++) {
                float v0 = acc[i][j][rh * 2] * inv;
                float v1 = acc[i][j][rh * 2 + 1] * inv;
                __nv_bfloat16 h0 = __float2bfloat16(v0);
                __nv_bfloat16 h1 = __float2bfloat16(v1);
                u32 hv = (u32)__bfloat16_as_ushort(h0)
                       | ((u32)__bfloat16_as_ushort(h1) << 16);
                u32 lv = pack_bf2(v0 - __bfloat162float(h0),
                                  v1 - __bfloat162float(h1));
                *(u32*)(g_nfh + base + j * 8 + qt * 2) = hv;
                *(u32*)(g_nfl + base + j * 8 + qt * 2) = lv;
            }
        }
}

// ---------------------------------------------------------------------------
// corr_kernel: parity Toeplitz GEMM, sp-SPLIT stages for 2 CTAs/SM.
// 36 iterations it2 = ((py*2 + chf)*2 + sp). f2 stage holds one split
// [par][72 rows][128B] = 18KB, ring-2. f1 resident (64KB). smem 107KB.
// sp=0: acc += Ah*Bh + Al*Bh ; sp=1: acc += Ah*Bl.
// ---------------------------------------------------------------------------
#define CORR_F2OFF  65536
#define CORR_F2BUF  18432
#define CORR_OUTOFF (65536 + 2 * 18432)
#define CORR_SMEM   (65536 + 2 * 18432 + 4800)   // 107200

__global__ __launch_bounds__(256, 2)
void corr_kernel(float* __restrict__ out) {
    extern __shared__ char smem[];
    const u32 sb = smem_u32(smem);
    const int tid  = threadIdx.x;
    const int wid  = tid >> 5;
    const int lane = tid & 31;
    const int h    = blockIdx.x;
    const int pb   = blockIdx.y;
    const int pair = pb >> 2, b = pb & 3;
    const int img1 = pair * 4 + b;
    const int img2 = img1 + 4;
    const int pp   = wid & 1;
    const int idx  = wid >> 1;
    const int qg = lane >> 2, qt = lane & 3;
    const int a_r0 = (lane & 7) + ((lane >> 3) & 1) * 8;
    const int a_cs = (lane >> 4) & 1;
    const int b_r0 = (lane & 7) + ((lane >> 4) & 1) * 8;
    const int b_cs = (lane >> 3) & 1;

    // ---- f1 prologue: [chalf][split][par][64 rows][128B]
    for (int t = tid; t < 4096; t += 256) {
        const int ch  = t & 7;
        const int row = (t >> 3) & 63;
        const int par = (t >> 9) & 1;
        const int sp  = (t >> 10) & 1;
        const int chf = (t >> 11) & 1;
        const int w   = par + 2 * row;
        const __nv_bfloat16* src = (sp ? g_nfl : g_nfh) +
            ((((size_t)img1 * HH + h) * WW + w) * CO + chf * 64 + ch * 8);
        const u32 dst = sb + (u32)((((chf * 2 + sp) * 2 + par) * 64 + row) * 128)
                      + (u32)((ch ^ (row & 7)) << 4);
        CP_ASYNC16(dst, src, 16u);
    }

    auto issue_f2 = [&](int it2) {         // it2 = ((py*2+chf)*2 + sp)
        const int py  = it2 >> 2;
        const int chf = (it2 >> 1) & 1;
        const int sp  = it2 & 1;
        const int h2  = h + 2 * py - 8;
        const bool hok = (unsigned)h2 < (unsigned)HH;
        const u32 buf = sb + CORR_F2OFF + (u32)(it2 & 1) * CORR_F2BUF;
        for (int t = tid; t < 1152; t += 256) {
            const int ch  = t & 7;
            const int rr  = t >> 3;        // 0..143
            const int row = rr % 72;       // colpad
            const int par = rr / 72;
            const int w2 = par + 2 * (row - 4);
            const bool ok = hok && (unsigned)w2 < (unsigned)WW;
            const __nv_bfloat16* src = (sp ? g_nfl : g_nfh) +
                ((((size_t)img2 * HH + (ok ? h2 : 0)) * WW + (ok ? w2 : 0)) * CO
                 + chf * 64 + ch * 8);
            const u32 dst = buf + (u32)((par * 72 + row) * 128)
                          + (u32)((ch ^ (row & 7)) << 4);
            CP_ASYNC16(dst, src, ok ? 16u : 0u);
        }
        CP_COMMIT();
    };

    issue_f2(0);                           // group 0 = f1 + f2(0)
    float acc[3][4];
    float* ost = (float*)(smem + CORR_OUTOFF);

    for (int it2 = 0; it2 < 36; it2++) {
        if (it2 + 1 < 36) { issue_f2(it2 + 1); CP_WAIT1(); }
        else              { CP_WAIT0(); }
        __syncthreads();
        const int chf = (it2 >> 1) & 1;
        const int sp  = it2 & 1;
        if ((it2 & 3) == 0) {
#pragma unroll
            for (int t2 = 0; t2 < 3; t2++)
#pragma unroll
                for (int c = 0; c < 4; c++) acc[t2][c] = 0.f;
        }
        const u32 f2b = sb + CORR_F2OFF + (u32)(it2 & 1) * CORR_F2BUF;
#pragma unroll
        for (int kk = 0; kk < 4; kk++) {
            u32 Ah[4], Al[4], Bx[6];
            {   // A from resident f1
                const int row = idx * 16 + a_r0;
                const int ch  = kk * 2 + a_cs;
                const u32 swz = (u32)((ch ^ (row & 7)) << 4);
                const u32 oh = sb + (u32)((((chf * 2 + 0) * 2 + pp) * 64 + row) * 128) + swz;
                LDM4(Ah, oh);
                if (sp == 0) {
                    const u32 ol = sb + (u32)((((chf * 2 + 1) * 2 + pp) * 64 + row) * 128) + swz;
                    LDM4(Al, ol);
                }
            }
            {   // B tiles 0,1 from the current f2 split stage
                const int row = idx * 16 + b_r0;
                const int ch  = kk * 2 + b_cs;
                const u32 swz = (u32)((ch ^ (row & 7)) << 4);
                LDM4(Bx, f2b + (u32)((pp * 72 + row) * 128) + swz);
            }
            {   // B tile 2 (cols +16..+23)
                const int row = idx * 16 + 16 + (lane & 7);
                const int ch  = kk * 2 + ((lane >> 3) & 1);
                const u32 swz = (u32)((ch ^ (row & 7)) << 4);
                LDM2(Bx + 4, f2b + (u32)((pp * 72 + row) * 128) + swz);
            }
#pragma unroll
            for (int t2 = 0; t2 < 3; t2++) {
                const u32 b0 = Bx[t2 * 2], b1 = Bx[t2 * 2 + 1];
                MMA16816(acc[t2], Ah, b0, b1);
                if (sp == 0) MMA16816(acc[t2], Al, b0, b1);
            }
        }
        if ((it2 & 3) == 3) {
            const int py = it2 >> 2;
#pragma unroll
            for (int t2 = 0; t2 < 3; t2++)
#pragma unroll
                for (int reg = 0; reg < 4; reg++) {
                    const int r  = qg + 8 * (reg >> 1);
                    const int j  = 8 * t2 + 2 * qt + (reg & 1);
                    const int px = j - r;
                    if ((unsigned)px <= 8u) {
                        const int w = pp + 2 * (16 * idx + r);
                        ost[px * 132 + w] = acc[t2][reg];
                    }
                }
            __syncthreads();
            for (int t2 = tid; t2 < 1152; t2 += 256) {
                const int px = t2 >> 7;
                const int w  = t2 & 127;
                out[(((size_t)b * 243 + pair * 81 + py * 9 + px) * HH + h) * WW + w]
                    = ost[px * 132 + w];
            }
        }
        __syncthreads();
    }
}

// ---------------------------------------------------------------------------
extern "C" void kernel_launch(void* const* d_in, const int* in_sizes, int n_in,
                              void* d_out, int out_size) {
    const float* x     = (const float*)d_in[0];
    const float* gamma = (const float*)d_in[1];
    const float* beta  = (const float*)d_in[2];
    const float* mean  = (const float*)d_in[3];
    const float* var   = (const float*)d_in[4];
    const float* convw = (const float*)d_in[5];
    float* out = (float*)d_out;

    cudaFuncSetAttribute(conv_kernel,
                         cudaFuncAttributeMaxDynamicSharedMemorySize, CONV_SMEM);
    cudaFuncSetAttribute(corr_kernel,
                         cudaFuncAttributeMaxDynamicSharedMemorySize, CORR_SMEM);

    prep_bn_kernel<<<1, 128>>>(gamma, beta, mean, var);
    prep_w_kernel<<<36, 256>>>(convw);
    act_split_kernel<<<dim3(NIMG, HH), 256>>>(x);
    conv_kernel<<<dim3(NIMG, HH), 256, CONV_SMEM>>>();
    corr_kernel<<<dim3(HH, 3 * BB), 256, CORR_SMEM>>>(out);
}